// round 17
// baseline (speedup 1.0000x reference)
#include <cuda_runtime.h>
#include <math.h>

#define P 262144          // 512*512
#define NCH 16
#define NIMG 8
#define NID 32            // ids 1..32 at row id-1; id 0 excluded
#define STR 17            // g_acc row stride
#define ACCN (NID * STR)  // 544
#define RREP 2            // replicas: smem 37KB -> STATIC shared, no attribute call
#define RS 18             // packed accum row: 8 f2 + count + pad
#define REPF 578          // replica stride floats (289 f2, == 1 mod 16 bankpairs)
#define WARPF (RREP * REPF)     // 1156 floats/warp
#define SMEMF (8 * WARPF)       // 9248 floats = 36,992 B static shared
#define DELTA_V 0.5f
#define DELTA_D 1.5f
#define GAMMA_W 0.001f
#define FULL 0xffffffffu

#define TPI 128                 // tasks per image per phase (2048 px each)
#define NACC (TPI * NIMG)       // 1024  (queue slots [0, NACC))
#define NTASK (2 * NACC)        // + 1024 var tasks
#define GRID 444                // 3 blocks/SM x 148 SMs, all resident

#define ADDX2(acc, val) do {                                                    \
    unsigned long long _a = *reinterpret_cast<unsigned long long*>(&(acc));     \
    unsigned long long _b = *reinterpret_cast<const unsigned long long*>(&(val));\
    asm("add.rn.f32x2 %0, %1, %2;" : "=l"(_a) : "l"(_a), "l"(_b));              \
    *reinterpret_cast<unsigned long long*>(&(acc)) = _a;                        \
} while (0)

// Scratch (zeroed at module load; k_post resets everything each run).
__device__ float g_acc[NIMG][ACCN];
__device__ float g_vsum[NIMG];
__device__ unsigned g_queue;          // task ticket
__device__ unsigned g_done[NIMG];     // completed accum tasks per image

__device__ __forceinline__ float wsum(float x) {
#pragma unroll
    for (int o = 16; o > 0; o >>= 1) x += __shfl_xor_sync(FULL, x, o);
    return x;
}

// ---- accum task: 2048 px of image img at offset bx*2048 (R10/R15-proven core) ----
__device__ __forceinline__ void accum_task(float* sm, int img, int bx,
                                           const float* __restrict__ emb,
                                           const int* __restrict__ mask,
                                           int tid, int w, int lane) {
    for (int i = tid; i < SMEMF; i += 256) sm[i] = 0.f;
    __syncthreads();

    const float* eb = emb + (size_t)img * NCH * P;
    const int*   mb = mask + (size_t)img * P;
    const int wbase = bx * 2048 + w * 256;
    const unsigned below = (1u << lane) - 1u;
    float* wacc = sm + w * WARPF;

    for (int it = 0; it < 4; ++it) {
        const int p0 = wbase + it * 64 + lane * 2;
        const int2 mid = *reinterpret_cast<const int2*>(mb + p0);
        float2 vv[2][8];
#pragma unroll
        for (int e = 0; e < NCH; e += 2) {
            const float2 ta = *reinterpret_cast<const float2*>(eb + (size_t)e * P + p0);
            const float2 tb = *reinterpret_cast<const float2*>(eb + (size_t)(e + 1) * P + p0);
            vv[0][e >> 1] = make_float2(ta.x, tb.x);
            vv[1][e >> 1] = make_float2(ta.y, tb.y);
        }
        const int ids[2] = {mid.x, mid.y};
#pragma unroll
        for (int s = 0; s < 2; s++) {
            const int id = ids[s];
            const bool go = (id != 0);
            const int key = go ? id : (64 + lane);
            const unsigned peers = __match_any_sync(FULL, key);
            const int rank = __popc(peers & below);
            const int band = rank >> 1;               // R=2: round = rank/2
            const int rep  = rank & 1;
            const float cntf = (float)__popc(peers);
            float* af = wacc + rep * REPF + (id - 1) * RS;
            float2* a2 = reinterpret_cast<float2*>(af);
            for (int r = 0;; r++) {
                if (!__ballot_sync(FULL, go && band >= r)) break;
                if (go && band == r) {
#pragma unroll
                    for (int j = 0; j < 8; j++) {
                        float2 c = a2[j];
                        ADDX2(c, vv[s][j]);
                        a2[j] = c;
                    }
                    if (rank == 0) af[16] += cntf;
                }
            }
        }
    }
    __syncthreads();

    for (int i = tid; i < ACCN; i += 256) {
        const int row = i / STR, e = i % STR;
        const int off = row * RS + e;
        float s = 0.f;
#pragma unroll
        for (int w2 = 0; w2 < 8; w2++) {
#pragma unroll
            for (int rp = 0; rp < RREP; rp++) s += sm[w2 * WARPF + rp * REPF + off];
        }
        atomicAdd(&g_acc[img][i], s);
    }
}

// ---- var task: 2048 px; adds sum(t*invc) to g_vsum[img] (R10-proven core) ----
__device__ __forceinline__ void var_task(float* sm, int img, int bx,
                                         const float* __restrict__ emb,
                                         const int* __restrict__ mask,
                                         int tid, int w, int lane) {
    float* mut = sm;                 // [ACCN]
    float* wred = sm + ACCN;         // [8]

    for (int i = tid; i < ACCN; i += 256) {
        const int row = i / STR, e = i % STR;
        const float cc = fmaxf(g_acc[img][row * STR + NCH], 1.f);
        mut[i] = (e == NCH) ? (1.f / cc) : (g_acc[img][row * STR + e] / cc);
    }
    __syncthreads();

    const float* eb = emb + (size_t)img * NCH * P;
    const int*   mb = mask + (size_t)img * P;
    const int wbase = bx * 2048 + w * 256;
    float vsum = 0.f;

    for (int it = 0; it < 4; ++it) {
        const int p0 = wbase + it * 64 + lane * 2;
        const int2 mid = *reinterpret_cast<const int2*>(mb + p0);
        float v[2][NCH];
#pragma unroll
        for (int e = 0; e < NCH; e++) {
            const float2 t = *reinterpret_cast<const float2*>(eb + (size_t)e * P + p0);
            v[0][e] = t.x; v[1][e] = t.y;
        }
        const int ids[2] = {mid.x, mid.y};
#pragma unroll
        for (int s = 0; s < 2; s++) {
            const int id = ids[s];
            const int row = ((id == 0) ? 1 : id) - 1;
            const float* mrow = &mut[row * STR];
            float sq = 0.f;
#pragma unroll
            for (int e = 0; e < NCH; e++) {
                const float d = v[s][e] - mrow[e];
                sq = fmaf(d, d, sq);
            }
            const float pd = (sq > 0.f) ? sqrtf(sq) : 0.f;
            const float tt = fmaxf(pd - DELTA_V, 0.f);
            vsum += (id != 0) ? (tt * tt * mrow[NCH]) : 0.f;
        }
    }

    vsum = wsum(vsum);
    if (lane == 0) wred[w] = vsum;
    __syncthreads();
    if (tid == 0) {
        float s = 0.f;
#pragma unroll
        for (int i = 0; i < 8; i++) s += wred[i];
        atomicAdd(&g_vsum[img], s);
    }
    __syncthreads();                 // sm reused next task
}

// Persistent worker: pops accum tasks [0,1024) then var tasks [1024,2048).
// Var tasks spin (bounded: queue is monotone, accum never waits) until their
// image's 128 accum tasks are done. No exit barriers, no finalize here.
__global__ __launch_bounds__(256, 3)
void k_fused(const float* __restrict__ emb, const int* __restrict__ mask) {
    __shared__ float sm[SMEMF];
    __shared__ unsigned s_task;
    const int tid = threadIdx.x, w = tid >> 5, lane = tid & 31;

    for (;;) {
        if (tid == 0) s_task = atomicAdd(&g_queue, 1u);
        __syncthreads();
        const unsigned t = s_task;
        __syncthreads();             // protect s_task before next overwrite
        if (t >= NTASK) return;

        if (t < NACC) {
            const int img = t >> 7, bx = t & 127;
            accum_task(sm, img, bx, emb, mask, tid, w, lane);
            __syncthreads();
            if (tid == 0) { __threadfence(); atomicAdd(&g_done[img], 1u); }
        } else {
            const unsigned vt = t - NACC;
            const int img = vt >> 7, bx = 127 - (int)(vt & 127);
            if (tid == 0) {
                while (atomicAdd(&g_done[img], 0u) < TPI) __nanosleep(128);
            }
            __syncthreads();
            __threadfence();         // acquire g_acc[img]
            var_task(sm, img, bx, emb, mask, tid, w, lane);
        }
    }
}

// Finalize + reset (stream-ordered after k_fused; all its writes are visible).
__global__ __launch_bounds__(256) void k_post(float* __restrict__ out) {
    __shared__ float smu[NIMG][32][NCH + 1];
    __shared__ float sv[NIMG], sd[NIMG], sr[NIMG], sva[NIMG];
    const int tid = threadIdx.x, w = tid >> 5, lane = tid & 31;

    const float* ga = g_acc[w];                 // warp = image
    const float cnt = ga[lane * STR + NCH];     // lane <-> instance lane+1
    const bool pres = cnt > 0.f;
    const float cc = fmaxf(cnt, 1.f);
    float mu[NCH];
#pragma unroll
    for (int e = 0; e < NCH; e++) {
        mu[e] = ga[lane * STR + e] / cc;
        smu[w][lane][e] = mu[e];
    }
    const float var_s = g_vsum[w];
    __syncwarp();

    const unsigned pb = __ballot_sync(FULL, pres);
    const float n_inst = (float)__popc(pb);

    float sqm = 0.f;
#pragma unroll
    for (int e = 0; e < NCH; e++) sqm = fmaf(mu[e], mu[e], sqm);
    const float reg_l = pres ? ((sqm > 0.f) ? sqrtf(sqm) : 0.f) : 0.f;

    float dsum = 0.f, pcount = 0.f;
#pragma unroll 4
    for (int b = 1; b < 32; b++) {
        float dsq = 0.f;
#pragma unroll
        for (int e = 0; e < NCH; e++) {
            const float d = mu[e] - smu[w][b][e];
            dsq = fmaf(d, d, dsq);
        }
        if ((lane < b) && pres && ((pb >> b) & 1u)) {
            const float dd = (dsq > 0.f) ? sqrtf(dsq) : 0.f;
            const float tt = fmaxf(2.f * DELTA_D - dd, 0.f);
            dsum = fmaf(tt, tt, dsum);
            pcount += 1.f;
        }
    }

    const float reg_t = wsum(reg_l);
    const float dst_t = wsum(dsum);
    const float pcs   = wsum(pcount);

    if (lane == 0) {
        const float valid = (n_inst > 0.f) ? 1.f : 0.f;
        const float denom = fmaxf(n_inst, 1.f);
        sv[w]  = (var_s / denom) * valid;
        sr[w]  = (reg_t / denom) * valid;
        sd[w]  = (dst_t / fmaxf(pcs, 1.f)) * ((n_inst > 1.f) ? 1.f : 0.f) * valid;
        sva[w] = valid;
    }
    __syncthreads();

    if (tid == 0) {
        float vs = 0.f, v = 0.f, d = 0.f, r = 0.f;
        for (int i = 0; i < NIMG; i++) { vs += sva[i]; v += sv[i]; d += sd[i]; r += sr[i]; }
        vs = fmaxf(vs, 1.f);
        v /= vs; d /= vs; r /= vs;
        out[0] = v + d + GAMMA_W * r;
        out[1] = v;
        out[2] = d;
        out[3] = r;
    }

    // Reset all scratch for the next graph replay.
    float* a = &g_acc[0][0];
    for (int i = tid; i < NIMG * ACCN; i += 256) a[i] = 0.f;
    if (tid < NIMG) { g_vsum[tid] = 0.f; g_done[tid] = 0u; }
    if (tid == 0) g_queue = 0u;
}

extern "C" void kernel_launch(void* const* d_in, const int* in_sizes, int n_in,
                              void* d_out, int out_size) {
    const float* emb = (const float*)d_in[0];
    const int* mask = (const int*)d_in[1];
    float* out = (float*)d_out;

    k_fused<<<GRID, 256>>>(emb, mask);
    k_post<<<1, 256>>>(out);
}